// round 5
// baseline (speedup 1.0000x reference)
#include <cuda_runtime.h>
#include <cstdint>

#define BATCH   8
#define NANCH   25200
#define NCH     85
#define TOPK    1000
#define KPAD    1024
#define NCLS    80
#define CONF_TH 0.25f
#define IOU_TH  0.45f
#define MAX_WH  4096.0f
#define NB14    16384
#define CAP     8192
#define RSTR    33

// ---------------- scratch (device globals; no allocation) ----------------
__device__ unsigned g_enc [BATCH * NANCH];
__device__ unsigned g_hist[BATCH * NB14];   // re-zeroed by k_nms each run

// ---------------- K1: score = obj * max(cls); encode; fused 14-bit histogram ----------------
#define SB 128
__global__ void __launch_bounds__(SB) k_score(const float* __restrict__ x) {
    __shared__ float sx[SB * NCH];
    const int tid = threadIdx.x;
    const size_t base = (size_t)blockIdx.x * SB * NCH;
    const float4* xv = (const float4*)(x + base);
    #pragma unroll
    for (int t = tid; t < SB * NCH / 4; t += SB) ((float4*)sx)[t] = xv[t];
    __syncthreads();

    const int a = blockIdx.x * SB + tid;
    const float* p = sx + tid * NCH;
    float obj = p[4];
    float m = p[5];
    #pragma unroll 16
    for (int c = 1; c < NCLS; ++c) m = fmaxf(m, p[5 + c]);
    float sc = __fmul_rn(obj, m);
    unsigned u = __float_as_uint((sc > CONF_TH) ? sc : -1.0f);
    unsigned e = (u & 0x80000000u) ? ~u : (u | 0x80000000u);
    g_enc[a] = e;

    int b = a / NANCH;
    unsigned addr = (unsigned)b * NB14 + (e >> 18);
    unsigned mm = __match_any_sync(0xffffffffu, addr);
    if ((tid & 31) == (__ffs(mm) - 1))
        atomicAdd(&g_hist[addr], (unsigned)__popc(mm));
}

// ---------------- K2: fused top-k select + sort + gather + sparse IoU + scan + output ----------------
#define PO_ROWS   0
#define PO_BOXO   135168
#define PO_BOXP   151552
#define PO_AREA   167936
#define PO_SCORE  172032
#define PO_CLSF   176128
#define PO_CLIST  180224
#define PO_CBASE  184320
#define PO_COFF   184832
#define PO_KEEPW  185344
#define PO_OUTK   185472
#define K3_SMEM   193664
// aliases inside rows region (valid until rows is zeroed):
#define AL_CAND   0        // u64[CAP] = 64KB
#define AL_HIST2  65536    // u32[2048]
#define AL_SCN2   73728    // u32[2048]

__global__ void __launch_bounds__(1024) k_nms(const float* __restrict__ x,
                                              float* __restrict__ out) {
    const int b   = blockIdx.x;
    const int tid = threadIdx.x;
    const int wid = tid >> 5, lane = tid & 31;
    extern __shared__ unsigned char sm[];
    unsigned* rows  = (unsigned*)(sm + PO_ROWS);
    float4*   boxo  = (float4*)  (sm + PO_BOXO);
    float4*   boxp  = (float4*)  (sm + PO_BOXP);
    float*    area  = (float*)   (sm + PO_AREA);
    float*    score = (float*)   (sm + PO_SCORE);
    float*    clsf  = (float*)   (sm + PO_CLSF);
    int*      clist = (int*)     (sm + PO_CLIST);
    int*      cbase = (int*)     (sm + PO_CBASE);
    int*      coff  = (int*)     (sm + PO_COFF);
    unsigned* keepw = (unsigned*)(sm + PO_KEEPW);
    unsigned long long* outk  = (unsigned long long*)(sm + PO_OUTK);
    unsigned long long* cand  = (unsigned long long*)(sm + AL_CAND);
    unsigned*           hist2 = (unsigned*)(sm + AL_HIST2);
    unsigned*           scn2  = (unsigned*)(sm + AL_SCN2);

    __shared__ unsigned s_w[32];
    __shared__ unsigned s_ctrl[4];          // [0]=bucket/gt [1]=need [2]=count [3]=cnt
    __shared__ unsigned long long s_T64;

    const unsigned* encb = g_enc + b * NANCH;

    // ---- Phase A: 16384-bucket suffix scan via warp shuffles (2 barriers) ----
    unsigned lv[16];
    const int base16 = tid * 16;
    #pragma unroll
    for (int i = 0; i < 16; ++i) lv[i] = g_hist[b * NB14 + base16 + i];
    #pragma unroll
    for (int i = 0; i < 16; ++i) g_hist[b * NB14 + base16 + i] = 0u;  // self-clean
    unsigned run = 0;
    #pragma unroll
    for (int i = 15; i >= 0; --i) { run += lv[i]; lv[i] = run; }      // local inclusive suffix
    const unsigned ttot = run;
    unsigned v = ttot;
    #pragma unroll
    for (int off = 1; off < 32; off <<= 1) {
        unsigned t = __shfl_down_sync(0xffffffffu, v, off);
        if (lane + off < 32) v += t;
    }
    if (lane == 0) s_w[wid] = v;            // warp totals
    __syncthreads();
    if (tid < 32) {
        unsigned u0 = s_w[tid], w = u0;
        #pragma unroll
        for (int off = 1; off < 32; off <<= 1) {
            unsigned t = __shfl_down_sync(0xffffffffu, w, off);
            if (tid + off < 32) w += t;
        }
        s_w[tid] = w - u0;                  // exclusive suffix from higher warps
    }
    __syncthreads();
    {
        unsigned above = s_w[wid] + (v - ttot);
        #pragma unroll
        for (int i = 0; i < 16; ++i) {
            unsigned tot = above + lv[i];
            unsigned cnt = lv[i] - ((i < 15) ? lv[i + 1] : 0u);
            unsigned gt  = tot - cnt;
            if (gt < TOPK && TOPK <= tot) {
                s_ctrl[0] = (unsigned)(base16 + i);
                s_ctrl[1] = TOPK - gt;
                s_ctrl[2] = cnt;
            }
        }
    }
    __syncthreads();

    unsigned long long prefix = (unsigned long long)s_ctrl[0];
    int shift = 50;
    unsigned need = s_ctrl[1], count = s_ctrl[2];
    bool haveT = false;
    unsigned long long T64 = 0;
    if (need == count) { T64 = prefix << shift; haveT = true; }

    // ---- Phase A2 (rare): refine bucket until candidates fit CAP ----
    while (!haveT && count > CAP) {
        int w = (shift >= 11) ? 11 : shift;
        int s2 = shift - w;
        unsigned dmask = (1u << w) - 1u;
        for (int t = tid; t < 2048; t += 1024) hist2[t] = 0u;
        __syncthreads();
        #pragma unroll
        for (int it = 0; it < 25; ++it) {
            int i = tid + it * 1024;
            if (i < NANCH) {
                unsigned long long key =
                    ((unsigned long long)encb[i] << 32) | (unsigned)(~(unsigned)i);
                if ((key >> shift) == prefix)
                    atomicAdd(&hist2[(unsigned)((key >> s2) & dmask)], 1u);
            }
        }
        __syncthreads();
        for (int t = tid; t < 2048; t += 1024) scn2[t] = hist2[t];
        __syncthreads();
        for (int d = 1; d < 2048; d <<= 1) {
            unsigned a0 = (tid + d < 2048) ? scn2[tid + d] : 0u;
            unsigned a1 = (tid + 1024 + d < 2048) ? scn2[tid + 1024 + d] : 0u;
            __syncthreads();
            scn2[tid] += a0; scn2[tid + 1024] += a1;
            __syncthreads();
        }
        #pragma unroll
        for (int q = 0; q < 2; ++q) {
            int d = tid + q * 1024;
            unsigned tot = scn2[d], gt = tot - hist2[d];
            if (gt < need && need <= tot) {
                s_ctrl[0] = (unsigned)d;
                s_ctrl[1] = need - gt;
                s_ctrl[2] = hist2[d];
            }
        }
        __syncthreads();
        prefix = (prefix << w) | (unsigned long long)s_ctrl[0];
        need = s_ctrl[1]; count = s_ctrl[2]; shift = s2;
        if (need == count) { T64 = prefix << shift; haveT = true; }
        __syncthreads();
    }

    // ---- Phase B/C: compact candidates; rank-by-count -> exact 1000th key ----
    if (!haveT) {
        if (tid == 0) s_ctrl[3] = 0u;
        __syncthreads();
        #pragma unroll
        for (int it = 0; it < 25; ++it) {
            int i = tid + it * 1024;
            if (i < NANCH) {
                unsigned long long key =
                    ((unsigned long long)encb[i] << 32) | (unsigned)(~(unsigned)i);
                if ((key >> shift) == prefix) {
                    unsigned pos = atomicAdd(&s_ctrl[3], 1u);
                    if (pos < CAP) cand[pos] = key;
                }
            }
        }
        __syncthreads();
        unsigned C = s_ctrl[3]; if (C > CAP) C = CAP;
        for (unsigned j = tid; j < C; j += 1024) {
            unsigned long long kj = cand[j];
            unsigned gt = 0;
            for (unsigned k = 0; k < C; ++k) gt += (cand[k] > kj);
            if (gt == need - 1) s_T64 = kj;
        }
        __syncthreads();
        T64 = s_T64;
    }
    __syncthreads();

    // ---- Phase D: collect the exactly-1000 keys >= T64 ----
    if (tid == 0) s_ctrl[3] = 0u;
    __syncthreads();
    #pragma unroll
    for (int it = 0; it < 25; ++it) {
        int i = tid + it * 1024;
        if (i < NANCH) {
            unsigned long long key =
                ((unsigned long long)encb[i] << 32) | (unsigned)(~(unsigned)i);
            if (key >= T64) {
                unsigned pos = atomicAdd(&s_ctrl[3], 1u);
                if (pos < KPAD) outk[pos] = key;
            }
        }
    }
    __syncthreads();
    const unsigned ncol = (s_ctrl[3] < KPAD) ? s_ctrl[3] : KPAD;

    // ---- Phase E: rank-by-count sort (desc), distinct keys -> unique ranks ----
    unsigned long long mykey = (tid < (int)ncol) ? outk[tid] : 0ull;
    cand[tid] = mykey;                       // cand region is free again
    __syncthreads();
    {
        unsigned r = 0;
        #pragma unroll 4
        for (int k = 0; k < KPAD; ++k) r += (cand[k] > mykey);
        __syncthreads();                     // all reads done before overwrite
        if (tid < (int)ncol) outk[r] = mykey;
        else                 outk[tid] = 0ull;
    }
    __syncthreads();

    // ---- Phase F: zero bitmat, decode + gather + argmax recompute ----
    for (int t = tid; t < KPAD * RSTR; t += 1024) rows[t] = 0u;
    if (tid < NCLS) coff[tid] = 0;
    if (tid < 32)   keepw[tid] = 0u;

    unsigned long long key = outk[tid];
    float sc = -1.0f;
    int   idx = 0;
    if (key != 0ull) {
        unsigned e = (unsigned)(key >> 32);
        unsigned u = (e & 0x80000000u) ? (e ^ 0x80000000u) : ~e;
        sc = __uint_as_float(u);
        idx = (int)(~(unsigned)(key & 0xffffffffull));
    }
    score[tid] = sc;
    int c = -1;
    if (tid < TOPK && key != 0ull) {
        const float* p = x + ((size_t)b * NANCH + idx) * NCH;
        float cx = p[0], cy = p[1], w = p[2], h = p[3];
        // argmax class (lowest index on ties, strict >)
        float best = p[5]; int bi = 0;
        #pragma unroll 8
        for (int cc = 1; cc < NCLS; ++cc) {
            float vv = p[5 + cc];
            if (vv > best) { best = vv; bi = cc; }
        }
        c = bi;
        float hw = __fmul_rn(w, 0.5f), hh = __fmul_rn(h, 0.5f);
        float x1 = __fsub_rn(cx, hw), y1 = __fsub_rn(cy, hh);
        float x2 = __fadd_rn(cx, hw), y2 = __fadd_rn(cy, hh);
        float cf = (float)c;
        float o  = __fmul_rn(cf, MAX_WH);
        float ox1 = __fadd_rn(x1, o), oy1 = __fadd_rn(y1, o);
        float ox2 = __fadd_rn(x2, o), oy2 = __fadd_rn(y2, o);
        boxp[tid] = make_float4(x1, y1, x2, y2);
        boxo[tid] = make_float4(ox1, oy1, ox2, oy2);
        area[tid] = __fmul_rn(__fsub_rn(ox2, ox1), __fsub_rn(oy2, oy1));
        clsf[tid] = cf;
    } else {
        boxp[tid] = make_float4(0.f, 0.f, 0.f, 0.f);
        boxo[tid] = make_float4(0.f, 0.f, 0.f, 0.f);
        area[tid] = 0.f; clsf[tid] = 0.f;
    }
    int V = __syncthreads_count(tid < TOPK && sc > CONF_TH);

    // ---- counting sort by class (cross-class IoU is exactly 0: offsets >= 4096 >> extent) ----
    if (c >= 0) atomicAdd(&coff[c], 1);
    __syncthreads();
    if (tid == 0) {
        int r2 = 0;
        #pragma unroll
        for (int k = 0; k < NCLS; ++k) { cbase[k] = r2; r2 += coff[k]; }
        cbase[NCLS] = r2;
    }
    __syncthreads();
    if (tid < NCLS) coff[tid] = cbase[tid];
    __syncthreads();
    if (c >= 0) clist[atomicAdd(&coff[c], 1)] = tid;
    __syncthreads();

    // ---- sparse IoU (reference fp32 arithmetic, FMA-free) ----
    if (c >= 0) {
        float4 bi4 = boxo[tid];
        float  ai  = area[tid];
        int k0 = cbase[c], k1 = cbase[c + 1];
        for (int k = k0; k < k1; ++k) {
            int j = clist[k];
            if (j == tid) continue;
            float4 bj = boxo[j];
            float ww = fmaxf(__fsub_rn(fminf(bi4.z, bj.z), fmaxf(bi4.x, bj.x)), 0.0f);
            float hh = fmaxf(__fsub_rn(fminf(bi4.w, bj.w), fmaxf(bi4.y, bj.y)), 0.0f);
            float inter = __fmul_rn(ww, hh);
            float den = __fadd_rn(__fsub_rn(__fadd_rn(ai, area[j]), inter), 1e-9f);
            if (__fdiv_rn(inter, den) > IOU_TH)
                rows[tid * RSTR + (j >> 5)] |= (1u << (j & 31));
        }
    }
    __syncthreads();

    // ---- windowed greedy scan (warp 0) ----
    if (tid < 32) {
        int nwin = (V + 31) >> 5;
        unsigned supp = 0;
        for (int widx = 0; widx < nwin; ++widx) {
            int i0 = widx << 5;
            int lim = V - i0;
            unsigned vmask = (lim >= 32) ? 0xffffffffu : ((1u << lim) - 1u);
            unsigned dw = rows[(i0 + lane) * RSTR + widx];
            unsigned ext = __shfl_sync(0xffffffffu, supp, widx);
            unsigned sw = ext | ~vmask;
            unsigned keep = 0;
            #pragma unroll
            for (int t = 0; t < 32; ++t) {
                unsigned dt = __shfl_sync(0xffffffffu, dw, t);
                if (!((sw >> t) & 1u)) { sw |= dt; keep |= (1u << t); }
            }
            unsigned acc = 0;
            #pragma unroll
            for (int t = 0; t < 32; ++t)
                if ((keep >> t) & 1u) acc |= rows[(i0 + t) * RSTR + lane];
            supp |= acc;
            if (lane == 0) keepw[widx] = keep;
        }
    }
    __syncthreads();

    // ---- output ----
    if (tid < TOPK) {
        bool keep = (keepw[tid >> 5] >> (tid & 31)) & 1u;
        float4 bx = boxp[tid];
        float so  = score[tid];
        float cf  = clsf[tid];
        if (!keep) { bx = make_float4(0.f, 0.f, 0.f, 0.f); so = 0.f; cf = 0.f; }
        float* o = out + ((size_t)b * TOPK + tid) * 6;
        o[0] = bx.x; o[1] = bx.y; o[2] = bx.z; o[3] = bx.w; o[4] = so; o[5] = cf;
    }
}

// ---------------- launcher ----------------
extern "C" void kernel_launch(void* const* d_in, const int* in_sizes, int n_in,
                              void* d_out, int out_size) {
    (void)in_sizes; (void)n_in; (void)out_size;
    const float* x = (const float*)d_in[0];
    float* out = (float*)d_out;
    cudaFuncSetAttribute(k_nms, cudaFuncAttributeMaxDynamicSharedMemorySize, K3_SMEM);

    k_score<<<(BATCH * NANCH) / SB, SB>>>(x);
    k_nms  <<<BATCH, 1024, K3_SMEM>>>(x, out);
}

// round 6
// speedup vs baseline: 1.1782x; 1.1782x over previous
#include <cuda_runtime.h>
#include <cstdint>

#define BATCH   8
#define NANCH   25200
#define NCH     85
#define TOPK    1000
#define KPAD    1024
#define NCLS    80
#define CONF_TH 0.25f
#define IOU_TH  0.45f
#define MAX_WH  4096.0f
#define NB14    16384
#define CAP     8192
#define RSTR    33

// ---------------- scratch (device globals; no allocation) ----------------
__device__ unsigned g_enc [BATCH * NANCH];
__device__ unsigned g_hist[BATCH * NB14];   // re-zeroed by k_nms each run

// ---------------- K1: score = obj * max(cls); encode; fused 14-bit histogram ----------------
#define SB 128
__global__ void __launch_bounds__(SB) k_score(const float* __restrict__ x) {
    __shared__ float sx[SB * NCH];
    const int tid = threadIdx.x;
    const size_t base = (size_t)blockIdx.x * SB * NCH;
    const float4* xv = (const float4*)(x + base);
    #pragma unroll
    for (int t = tid; t < SB * NCH / 4; t += SB) ((float4*)sx)[t] = xv[t];
    __syncthreads();

    const int a = blockIdx.x * SB + tid;
    const float* p = sx + tid * NCH;
    float obj = p[4];
    float m = p[5];
    #pragma unroll 16
    for (int c = 1; c < NCLS; ++c) m = fmaxf(m, p[5 + c]);
    float sc = __fmul_rn(obj, m);
    unsigned u = __float_as_uint((sc > CONF_TH) ? sc : -1.0f);
    unsigned e = (u & 0x80000000u) ? ~u : (u | 0x80000000u);
    g_enc[a] = e;

    int b = a / NANCH;
    unsigned addr = (unsigned)b * NB14 + (e >> 18);
    unsigned mm = __match_any_sync(0xffffffffu, addr);
    if ((tid & 31) == (__ffs(mm) - 1))
        atomicAdd(&g_hist[addr], (unsigned)__popc(mm));
}

// ---------------- K2: fused top-k select + sort + gather + sparse IoU + scan + output ----------------
#define PO_ROWS   0
#define PO_BOXO   135168
#define PO_BOXP   151552
#define PO_AREA   167936
#define PO_SCORE  172032
#define PO_CLSF   176128
#define PO_CLIST  180224
#define PO_CBASE  184320
#define PO_COFF   184832
#define PO_KEEPW  185344
#define PO_OUTK   185472
#define K3_SMEM   193664
// aliases inside rows region (valid until rows is zeroed in Phase F):
#define AL_STAGE  0        // u32[NB14] = 64KB (Phase A) ; u64[CAP] cand (Phase B/C)
#define AL_HIST2  65536    // u32[2048]
#define AL_SCN2   73728    // u32[2048]

__global__ void __launch_bounds__(1024) k_nms(const float* __restrict__ x,
                                              float* __restrict__ out) {
    const int b   = blockIdx.x;
    const int tid = threadIdx.x;
    const int wid = tid >> 5, lane = tid & 31;
    extern __shared__ unsigned char sm[];
    unsigned* rows  = (unsigned*)(sm + PO_ROWS);
    float4*   boxo  = (float4*)  (sm + PO_BOXO);
    float4*   boxp  = (float4*)  (sm + PO_BOXP);
    float*    area  = (float*)   (sm + PO_AREA);
    float*    score = (float*)   (sm + PO_SCORE);
    float*    clsf  = (float*)   (sm + PO_CLSF);
    int*      clist = (int*)     (sm + PO_CLIST);
    int*      cbase = (int*)     (sm + PO_CBASE);
    int*      coff  = (int*)     (sm + PO_COFF);
    unsigned* keepw = (unsigned*)(sm + PO_KEEPW);
    unsigned long long* outk   = (unsigned long long*)(sm + PO_OUTK);
    unsigned*           hstage = (unsigned*)(sm + AL_STAGE);
    unsigned long long* cand   = (unsigned long long*)(sm + AL_STAGE);
    unsigned*           hist2  = (unsigned*)(sm + AL_HIST2);
    unsigned*           scn2   = (unsigned*)(sm + AL_SCN2);

    __shared__ unsigned s_w[32];
    __shared__ unsigned s_ctrl[4];          // [0]=bucket [1]=need [2]=count [3]=cnt
    __shared__ unsigned long long s_T64;

    const unsigned* encb = g_enc + b * NANCH;

    // ---- Phase A: stage histogram coalesced, then 16384-bucket suffix scan ----
    #pragma unroll
    for (int q = 0; q < 16; ++q) {
        int i = tid + q * 1024;
        hstage[i] = g_hist[b * NB14 + i];
        g_hist[b * NB14 + i] = 0u;          // coalesced self-clean
    }
    __syncthreads();

    unsigned lv[16];
    const int base16 = tid * 16;
    #pragma unroll
    for (int i = 0; i < 16; ++i) lv[i] = hstage[base16 + i];
    unsigned run = 0;
    #pragma unroll
    for (int i = 15; i >= 0; --i) { run += lv[i]; lv[i] = run; }      // local inclusive suffix
    const unsigned ttot = run;
    unsigned v = ttot;
    #pragma unroll
    for (int off = 1; off < 32; off <<= 1) {
        unsigned t = __shfl_down_sync(0xffffffffu, v, off);
        if (lane + off < 32) v += t;
    }
    if (lane == 0) s_w[wid] = v;            // warp totals
    __syncthreads();
    if (tid < 32) {
        unsigned u0 = s_w[tid], w = u0;
        #pragma unroll
        for (int off = 1; off < 32; off <<= 1) {
            unsigned t = __shfl_down_sync(0xffffffffu, w, off);
            if (tid + off < 32) w += t;
        }
        s_w[tid] = w - u0;                  // exclusive suffix from higher warps
    }
    __syncthreads();
    {
        unsigned above = s_w[wid] + (v - ttot);
        #pragma unroll
        for (int i = 0; i < 16; ++i) {
            unsigned tot = above + lv[i];
            unsigned cnt = lv[i] - ((i < 15) ? lv[i + 1] : 0u);
            unsigned gt  = tot - cnt;
            if (gt < TOPK && TOPK <= tot) {
                s_ctrl[0] = (unsigned)(base16 + i);
                s_ctrl[1] = TOPK - gt;
                s_ctrl[2] = cnt;
            }
        }
    }
    __syncthreads();

    unsigned long long prefix = (unsigned long long)s_ctrl[0];
    int shift = 50;
    unsigned need = s_ctrl[1], count = s_ctrl[2];
    bool haveT = false;
    unsigned long long T64 = 0;
    if (need == count) { T64 = prefix << shift; haveT = true; }

    // ---- Phase A2 (rare): refine bucket until candidates fit CAP ----
    while (!haveT && count > CAP) {
        int w = (shift >= 11) ? 11 : shift;
        int s2 = shift - w;
        unsigned dmask = (1u << w) - 1u;
        for (int t = tid; t < 2048; t += 1024) hist2[t] = 0u;
        __syncthreads();
        for (int it = 0; it < 25; ++it) {
            int i = tid + it * 1024;
            if (i < NANCH) {
                unsigned long long key =
                    ((unsigned long long)encb[i] << 32) | (unsigned)(~(unsigned)i);
                if ((key >> shift) == prefix)
                    atomicAdd(&hist2[(unsigned)((key >> s2) & dmask)], 1u);
            }
        }
        __syncthreads();
        for (int t = tid; t < 2048; t += 1024) scn2[t] = hist2[t];
        __syncthreads();
        for (int d = 1; d < 2048; d <<= 1) {
            unsigned a0 = (tid + d < 2048) ? scn2[tid + d] : 0u;
            unsigned a1 = (tid + 1024 + d < 2048) ? scn2[tid + 1024 + d] : 0u;
            __syncthreads();
            scn2[tid] += a0; scn2[tid + 1024] += a1;
            __syncthreads();
        }
        #pragma unroll
        for (int q = 0; q < 2; ++q) {
            int d = tid + q * 1024;
            unsigned tot = scn2[d], gt = tot - hist2[d];
            if (gt < need && need <= tot) {
                s_ctrl[0] = (unsigned)d;
                s_ctrl[1] = need - gt;
                s_ctrl[2] = hist2[d];
            }
        }
        __syncthreads();
        prefix = (prefix << w) | (unsigned long long)s_ctrl[0];
        need = s_ctrl[1]; count = s_ctrl[2]; shift = s2;
        if (need == count) { T64 = prefix << shift; haveT = true; }
        __syncthreads();
    }

    // ---- Phase B/C: compact candidates; rank-by-count -> exact 1000th key ----
    if (!haveT) {
        if (tid == 0) s_ctrl[3] = 0u;
        __syncthreads();
        for (int it = 0; it < 25; ++it) {
            int i = tid + it * 1024;
            if (i < NANCH) {
                unsigned long long key =
                    ((unsigned long long)encb[i] << 32) | (unsigned)(~(unsigned)i);
                if ((key >> shift) == prefix) {
                    unsigned pos = atomicAdd(&s_ctrl[3], 1u);
                    if (pos < CAP) cand[pos] = key;
                }
            }
        }
        __syncthreads();
        unsigned C = s_ctrl[3]; if (C > CAP) C = CAP;
        for (unsigned j = tid; j < C; j += 1024) {
            unsigned long long kj = cand[j];
            unsigned gt = 0;
            for (unsigned k = 0; k < C; ++k) gt += (cand[k] > kj);
            if (gt == need - 1) s_T64 = kj;
        }
        __syncthreads();
        T64 = s_T64;
    }
    __syncthreads();

    // ---- Phase D: collect the exactly-1000 keys >= T64 ----
    if (tid == 0) s_ctrl[3] = 0u;
    __syncthreads();
    for (int it = 0; it < 25; ++it) {
        int i = tid + it * 1024;
        if (i < NANCH) {
            unsigned long long key =
                ((unsigned long long)encb[i] << 32) | (unsigned)(~(unsigned)i);
            if (key >= T64) {
                unsigned pos = atomicAdd(&s_ctrl[3], 1u);
                if (pos < KPAD) outk[pos] = key;
            }
        }
    }
    __syncthreads();
    const unsigned ncol = (s_ctrl[3] < KPAD) ? s_ctrl[3] : KPAD;
    if (tid >= (int)ncol) outk[tid] = 0ull;   // pad
    __syncthreads();

    // ---- Phase E: bitonic sort 1024 descending (distinct keys; zeros sink to tail) ----
    for (unsigned kk = 2; kk <= 1024; kk <<= 1) {
        for (unsigned j = kk >> 1; j > 0; j >>= 1) {
            unsigned i = (unsigned)tid, ixj = i ^ j;
            if (ixj > i) {
                unsigned long long a = outk[i], bb = outk[ixj];
                bool desc = ((i & kk) == 0);
                if (desc ? (a < bb) : (a > bb)) { outk[i] = bb; outk[ixj] = a; }
            }
            __syncthreads();
        }
    }

    // ---- Phase F: zero bitmat, decode + gather + argmax recompute ----
    for (int t = tid; t < KPAD * RSTR; t += 1024) rows[t] = 0u;
    if (tid < NCLS) coff[tid] = 0;
    if (tid < 32)   keepw[tid] = 0u;

    unsigned long long key = outk[tid];
    float sc = -1.0f;
    int   idx = 0;
    if (key != 0ull) {
        unsigned e = (unsigned)(key >> 32);
        unsigned u = (e & 0x80000000u) ? (e ^ 0x80000000u) : ~e;
        sc = __uint_as_float(u);
        idx = (int)(~(unsigned)(key & 0xffffffffull));
    }
    score[tid] = sc;
    int c = -1;
    if (tid < TOPK && key != 0ull) {
        const float* p = x + ((size_t)b * NANCH + idx) * NCH;
        float cx = p[0], cy = p[1], w = p[2], h = p[3];
        float best = p[5]; int bi = 0;
        #pragma unroll 8
        for (int cc = 1; cc < NCLS; ++cc) {
            float vv = p[5 + cc];
            if (vv > best) { best = vv; bi = cc; }   // strict >: lowest index on ties
        }
        c = bi;
        float hw = __fmul_rn(w, 0.5f), hh = __fmul_rn(h, 0.5f);
        float x1 = __fsub_rn(cx, hw), y1 = __fsub_rn(cy, hh);
        float x2 = __fadd_rn(cx, hw), y2 = __fadd_rn(cy, hh);
        float cf = (float)c;
        float o  = __fmul_rn(cf, MAX_WH);
        float ox1 = __fadd_rn(x1, o), oy1 = __fadd_rn(y1, o);
        float ox2 = __fadd_rn(x2, o), oy2 = __fadd_rn(y2, o);
        boxp[tid] = make_float4(x1, y1, x2, y2);
        boxo[tid] = make_float4(ox1, oy1, ox2, oy2);
        area[tid] = __fmul_rn(__fsub_rn(ox2, ox1), __fsub_rn(oy2, oy1));
        clsf[tid] = cf;
    } else {
        boxp[tid] = make_float4(0.f, 0.f, 0.f, 0.f);
        boxo[tid] = make_float4(0.f, 0.f, 0.f, 0.f);
        area[tid] = 0.f; clsf[tid] = 0.f;
    }
    int V = __syncthreads_count(tid < TOPK && sc > CONF_TH);

    // ---- counting sort by class (cross-class IoU exactly 0: offsets >= 4096 >> extent) ----
    if (c >= 0) atomicAdd(&coff[c], 1);
    __syncthreads();
    if (tid == 0) {
        int r2 = 0;
        #pragma unroll
        for (int k = 0; k < NCLS; ++k) { cbase[k] = r2; r2 += coff[k]; }
        cbase[NCLS] = r2;
    }
    __syncthreads();
    if (tid < NCLS) coff[tid] = cbase[tid];
    __syncthreads();
    if (c >= 0) clist[atomicAdd(&coff[c], 1)] = tid;
    __syncthreads();

    // ---- sparse IoU (reference fp32 arithmetic, FMA-free) ----
    if (c >= 0) {
        float4 bi4 = boxo[tid];
        float  ai  = area[tid];
        int k0 = cbase[c], k1 = cbase[c + 1];
        for (int k = k0; k < k1; ++k) {
            int j = clist[k];
            if (j == tid) continue;
            float4 bj = boxo[j];
            float ww = fmaxf(__fsub_rn(fminf(bi4.z, bj.z), fmaxf(bi4.x, bj.x)), 0.0f);
            float hh = fmaxf(__fsub_rn(fminf(bi4.w, bj.w), fmaxf(bi4.y, bj.y)), 0.0f);
            float inter = __fmul_rn(ww, hh);
            float den = __fadd_rn(__fsub_rn(__fadd_rn(ai, area[j]), inter), 1e-9f);
            if (__fdiv_rn(inter, den) > IOU_TH)
                rows[tid * RSTR + (j >> 5)] |= (1u << (j & 31));
        }
    }
    __syncthreads();

    // ---- windowed greedy scan (warp 0) ----
    if (tid < 32) {
        int nwin = (V + 31) >> 5;
        unsigned supp = 0;
        for (int widx = 0; widx < nwin; ++widx) {
            int i0 = widx << 5;
            int lim = V - i0;
            unsigned vmask = (lim >= 32) ? 0xffffffffu : ((1u << lim) - 1u);
            unsigned dw = rows[(i0 + lane) * RSTR + widx];
            unsigned ext = __shfl_sync(0xffffffffu, supp, widx);
            unsigned sw = ext | ~vmask;
            unsigned keep = 0;
            #pragma unroll
            for (int t = 0; t < 32; ++t) {
                unsigned dt = __shfl_sync(0xffffffffu, dw, t);
                if (!((sw >> t) & 1u)) { sw |= dt; keep |= (1u << t); }
            }
            unsigned acc = 0;
            #pragma unroll
            for (int t = 0; t < 32; ++t)
                if ((keep >> t) & 1u) acc |= rows[(i0 + t) * RSTR + lane];
            supp |= acc;
            if (lane == 0) keepw[widx] = keep;
        }
    }
    __syncthreads();

    // ---- output ----
    if (tid < TOPK) {
        bool keep = (keepw[tid >> 5] >> (tid & 31)) & 1u;
        float4 bx = boxp[tid];
        float so  = score[tid];
        float cf  = clsf[tid];
        if (!keep) { bx = make_float4(0.f, 0.f, 0.f, 0.f); so = 0.f; cf = 0.f; }
        float* o = out + ((size_t)b * TOPK + tid) * 6;
        o[0] = bx.x; o[1] = bx.y; o[2] = bx.z; o[3] = bx.w; o[4] = so; o[5] = cf;
    }
}

// ---------------- launcher ----------------
extern "C" void kernel_launch(void* const* d_in, const int* in_sizes, int n_in,
                              void* d_out, int out_size) {
    (void)in_sizes; (void)n_in; (void)out_size;
    const float* x = (const float*)d_in[0];
    float* out = (float*)d_out;
    cudaFuncSetAttribute(k_nms, cudaFuncAttributeMaxDynamicSharedMemorySize, K3_SMEM);

    k_score<<<(BATCH * NANCH) / SB, SB>>>(x);
    k_nms  <<<BATCH, 1024, K3_SMEM>>>(x, out);
}